// round 1
// baseline (speedup 1.0000x reference)
#include <cuda_runtime.h>

// ---------------------------------------------------------------------------
// Problem constants (fixed shapes per reference setup_inputs)
// ---------------------------------------------------------------------------
namespace {
constexpr int NPTS = 16384;
constexpr int BSZ  = 2;
constexpr int NKP  = 64;
constexpr int FD   = 64;
constexpr int KNN  = 64;
constexpr float RAD2 = 2.25f;   // 1.5^2

// Output layout: concat of flattened (T, D, G, H)
constexpr int SZ_T  = BSZ * NKP * NKP * 16;   // 131072
constexpr int SZ_D  = BSZ * NKP * NKP;        // 8192
constexpr int SZ_G  = BSZ * NKP * FD * 4;     // 32768
constexpr int OFF_T = 0;
constexpr int OFF_D = SZ_T;
constexpr int OFF_G = OFF_D + SZ_D;
constexpr int OFF_H = OFF_G + SZ_G;
}

// ---------------------------------------------------------------------------
// Kernel 1: fused ball-query (first-64-by-index within radius) + moment matrix
// One block per (side, b, kp). 256 threads.
// Writes normalized G_kp / H_kp (64x4 per keypoint) straight into d_out.
// ---------------------------------------------------------------------------
__global__ void __launch_bounds__(256)
ume_moments_kernel(const float* __restrict__ s_pts, const float* __restrict__ s_ft,
                   const float* __restrict__ s_kp,
                   const float* __restrict__ t_pts, const float* __restrict__ t_ft,
                   const float* __restrict__ t_kp,
                   float* __restrict__ out)
{
    const int side = blockIdx.y;
    const float* pts = side ? t_pts : s_pts;
    const float* ft  = side ? t_ft  : s_ft;
    const float* kp  = side ? t_kp  : s_kp;
    float* gout = out + (side ? OFF_H : OFF_G);

    const int b   = blockIdx.x >> 6;
    const int kk  = blockIdx.x & 63;
    const int tid = threadIdx.x;
    const int lane = tid & 31;
    const int wid  = tid >> 5;

    const float kx = kp[(b * NKP + kk) * 3 + 0];
    const float ky = kp[(b * NKP + kk) * 3 + 1];
    const float kz = kp[(b * NKP + kk) * 3 + 2];

    __shared__ int   s_idx[KNN];
    __shared__ int   s_wcnt[8];
    __shared__ int   s_cnt;
    __shared__ float s_red[256];
    __shared__ float s_den;

    if (tid == 0) s_cnt = 0;
    __syncthreads();

    const float* bp = pts + (size_t)b * NPTS * 3;

    // Ordered selection of the first up-to-64 in-radius indices.
    for (int base = 0; base < NPTS; base += 256) {
        if (s_cnt >= KNN) break;
        const int j = base + tid;
        const float dx = bp[j * 3 + 0] - kx;
        const float dy = bp[j * 3 + 1] - ky;
        const float dz = bp[j * 3 + 2] - kz;
        const bool hit = (dx * dx + dy * dy + dz * dz) < RAD2;
        const unsigned m = __ballot_sync(0xffffffffu, hit);
        if (lane == 0) s_wcnt[wid] = __popc(m);
        __syncthreads();
        int pre = 0, tot = 0;
        #pragma unroll
        for (int w = 0; w < 8; ++w) {
            const int c = s_wcnt[w];
            pre += (w < wid) ? c : 0;
            tot += c;
        }
        const int pos = s_cnt + pre + __popc(m & ((1u << lane) - 1u));
        if (hit && pos < KNN) s_idx[pos] = j;
        __syncthreads();
        if (tid == 0) s_cnt += tot;
        __syncthreads();
    }

    const int cnt = min(s_cnt, KNN);

    // Moments: thread (f, c): c==0 -> m0[f], c in 1..3 -> m1[f][c-1]
    const int f = tid >> 2;
    const int c = tid & 3;
    const float* bft = ft + (size_t)b * NPTS * FD;

    double acc = 0.0;
    for (int q = 0; q < cnt; ++q) {
        const int idx = s_idx[q];
        const float w = bft[(size_t)idx * FD + f];
        const float p = (c == 0) ? 1.0f : bp[idx * 3 + (c - 1)];
        acc += (double)w * (double)p;
    }
    s_red[tid] = (float)acc;
    __syncthreads();
    if (tid == 0) {
        double ds = 0.0;
        for (int q = 0; q < FD; ++q) ds += (double)s_red[q * 4];  // sum of m0
        s_den = (float)(ds + 1e-6);
    }
    __syncthreads();
    gout[((size_t)(b * NKP + kk) * FD + f) * 4 + c] = (float)acc / s_den;
}

// ---------------------------------------------------------------------------
// Kernel 2: one warp per (b, i_src, j_tgt) pair. Computes S=H^T G, Pg=G^T G,
// Ph=H^T H in fp64, then 3x3 Kabsch rotation + translation (T) and subspace
// distance D via Cholesky (equivalent to the reference's QR projector diff).
// ---------------------------------------------------------------------------
__global__ void __launch_bounds__(256)
ume_pair_kernel(float* __restrict__ out)
{
    const int warp = (blockIdx.x << 3) + (threadIdx.x >> 5);
    const int lane = threadIdx.x & 31;

    const int b = warp >> 12;
    const int i = (warp >> 6) & 63;   // source kp
    const int j = warp & 63;          // target kp

    const float4* G = reinterpret_cast<const float4*>(out + OFF_G) + (size_t)(b * NKP + i) * FD;
    const float4* H = reinterpret_cast<const float4*>(out + OFF_H) + (size_t)(b * NKP + j) * FD;

    double S[16], PG[10], PH[10];
    #pragma unroll
    for (int t = 0; t < 16; ++t) S[t] = 0.0;
    #pragma unroll
    for (int t = 0; t < 10; ++t) { PG[t] = 0.0; PH[t] = 0.0; }

    #pragma unroll
    for (int rr = 0; rr < 2; ++rr) {
        const int f = lane + rr * 32;
        const float4 gr = G[f];
        const float4 hr = H[f];
        const double g0 = gr.x, g1 = gr.y, g2 = gr.z, g3 = gr.w;
        const double h0 = hr.x, h1 = hr.y, h2 = hr.z, h3 = hr.w;

        S[0]  += h0 * g0; S[1]  += h0 * g1; S[2]  += h0 * g2; S[3]  += h0 * g3;
        S[4]  += h1 * g0; S[5]  += h1 * g1; S[6]  += h1 * g2; S[7]  += h1 * g3;
        S[8]  += h2 * g0; S[9]  += h2 * g1; S[10] += h2 * g2; S[11] += h2 * g3;
        S[12] += h3 * g0; S[13] += h3 * g1; S[14] += h3 * g2; S[15] += h3 * g3;

        // packed lower triangle: (0,0)(1,0)(1,1)(2,0)(2,1)(2,2)(3,0)(3,1)(3,2)(3,3)
        PG[0] += g0 * g0; PG[1] += g1 * g0; PG[2] += g1 * g1;
        PG[3] += g2 * g0; PG[4] += g2 * g1; PG[5] += g2 * g2;
        PG[6] += g3 * g0; PG[7] += g3 * g1; PG[8] += g3 * g2; PG[9] += g3 * g3;

        PH[0] += h0 * h0; PH[1] += h1 * h0; PH[2] += h1 * h1;
        PH[3] += h2 * h0; PH[4] += h2 * h1; PH[5] += h2 * h2;
        PH[6] += h3 * h0; PH[7] += h3 * h1; PH[8] += h3 * h2; PH[9] += h3 * h3;
    }

    // Warp butterfly reductions
    #pragma unroll
    for (int t = 0; t < 16; ++t)
        #pragma unroll
        for (int off = 16; off > 0; off >>= 1)
            S[t] += __shfl_xor_sync(0xffffffffu, S[t], off);
    #pragma unroll
    for (int t = 0; t < 10; ++t)
        #pragma unroll
        for (int off = 16; off > 0; off >>= 1)
            PG[t] += __shfl_xor_sync(0xffffffffu, PG[t], off);
    #pragma unroll
    for (int t = 0; t < 10; ++t)
        #pragma unroll
        for (int off = 16; off > 0; off >>= 1)
            PH[t] += __shfl_xor_sync(0xffffffffu, PH[t], off);

    if (lane != 0) return;

    // ---- scalar epilogue (fp64) -------------------------------------------
    double Sm[4][4];
    #pragma unroll
    for (int a = 0; a < 4; ++a)
        #pragma unroll
        for (int bb = 0; bb < 4; ++bb) Sm[a][bb] = S[a * 4 + bb];

    double Pg[4][4], Ph[4][4];
    {
        int idx = 0;
        for (int a = 0; a < 4; ++a)
            for (int bb = 0; bb <= a; ++bb) {
                Pg[a][bb] = Pg[bb][a] = PG[idx];
                Ph[a][bb] = Ph[bb][a] = PH[idx];
                ++idx;
            }
    }

    const double denl = Pg[0][0] + 2e-16;   // mg_sq(+eps) + eps
    const double denr = Sm[0][0] + 1e-16;   // mg_mh + eps
    double wlc[3], wrc[3];
    #pragma unroll
    for (int d = 0; d < 3; ++d) {
        wlc[d] = Pg[d + 1][0] / denl;
        wrc[d] = Sm[d + 1][0] / denr;
    }

    // A = M^T, M[i',j'] = sum_f right[f,i'] left[f,j']
    double A[3][3];
    #pragma unroll
    for (int a = 0; a < 3; ++a)
        #pragma unroll
        for (int bb = 0; bb < 3; ++bb)
            A[a][bb] = Sm[1 + bb][1 + a] - wrc[bb] * Sm[0][1 + a]
                     - wlc[a] * Sm[1 + bb][0] + wrc[bb] * wlc[a] * Sm[0][0];

    // Jacobi eigendecomposition of B = A^T A -> V, then Kabsch rotation.
    double B[3][3];
    #pragma unroll
    for (int r = 0; r < 3; ++r)
        #pragma unroll
        for (int c = 0; c < 3; ++c) {
            double s = 0.0;
            for (int k = 0; k < 3; ++k) s += A[k][r] * A[k][c];
            B[r][c] = s;
        }
    double V[3][3] = {{1, 0, 0}, {0, 1, 0}, {0, 0, 1}};
    for (int sweep = 0; sweep < 25; ++sweep) {
        const double off = fabs(B[0][1]) + fabs(B[0][2]) + fabs(B[1][2]);
        const double dia = fabs(B[0][0]) + fabs(B[1][1]) + fabs(B[2][2]);
        if (off <= 1e-30 * (dia + 1e-300)) break;
        for (int pq = 0; pq < 3; ++pq) {
            const int p = (pq == 2) ? 1 : 0;
            const int q = (pq == 0) ? 1 : 2;
            const double bpq = B[p][q];
            if (bpq == 0.0) continue;
            const double tau = (B[q][q] - B[p][p]) / (2.0 * bpq);
            const double t = ((tau >= 0.0) ? 1.0 : -1.0) / (fabs(tau) + sqrt(1.0 + tau * tau));
            const double c = 1.0 / sqrt(1.0 + t * t);
            const double s = t * c;
            for (int k = 0; k < 3; ++k) {
                const double bkp = B[k][p], bkq = B[k][q];
                B[k][p] = c * bkp - s * bkq; B[k][q] = s * bkp + c * bkq;
            }
            for (int k = 0; k < 3; ++k) {
                const double bpk = B[p][k], bqk = B[q][k];
                B[p][k] = c * bpk - s * bqk; B[q][k] = s * bpk + c * bqk;
            }
            for (int k = 0; k < 3; ++k) {
                const double vkp = V[k][p], vkq = V[k][q];
                V[k][p] = c * vkp - s * vkq; V[k][q] = s * vkp + c * vkq;
            }
        }
    }
    // sort eigenvalues descending
    int o0 = 0, o1 = 1, o2 = 2;
    {
        const double e0 = B[0][0], e1 = B[1][1], e2 = B[2][2];
        double ea = e0, eb = e1, ec = e2;
        if (ea < eb) { int t = o0; o0 = o1; o1 = t; double u = ea; ea = eb; eb = u; }
        if (ea < ec) { int t = o0; o0 = o2; o2 = t; double u = ea; ea = ec; ec = u; }
        if (eb < ec) { int t = o1; o1 = o2; o2 = t; double u = eb; eb = ec; ec = u; }
    }
    const double v0[3] = {V[0][o0], V[1][o0], V[2][o0]};
    const double v1[3] = {V[0][o1], V[1][o1], V[2][o1]};
    const double v2[3] = {v0[1] * v1[2] - v0[2] * v1[1],
                          v0[2] * v1[0] - v0[0] * v1[2],
                          v0[0] * v1[1] - v0[1] * v1[0]};

    double R[3][3] = {{1, 0, 0}, {0, 1, 0}, {0, 0, 1}};
    {
        double u0[3], u1[3];
        #pragma unroll
        for (int r = 0; r < 3; ++r) {
            u0[r] = A[r][0] * v0[0] + A[r][1] * v0[1] + A[r][2] * v0[2];
            u1[r] = A[r][0] * v1[0] + A[r][1] * v1[1] + A[r][2] * v1[2];
        }
        const double n0 = sqrt(u0[0] * u0[0] + u0[1] * u0[1] + u0[2] * u0[2]);
        if (n0 > 1e-150) {
            for (int r = 0; r < 3; ++r) u0[r] /= n0;
            const double d01 = u0[0] * u1[0] + u0[1] * u1[1] + u0[2] * u1[2];
            for (int r = 0; r < 3; ++r) u1[r] -= d01 * u0[r];
            double n1 = sqrt(u1[0] * u1[0] + u1[1] * u1[1] + u1[2] * u1[2]);
            if (n1 > 1e-14 * n0) {
                for (int r = 0; r < 3; ++r) u1[r] /= n1;
            } else {
                // arbitrary unit vector perpendicular to u0
                double t[3] = {0, 0, 0};
                t[(fabs(u0[0]) < 0.9) ? 0 : 1] = 1.0;
                const double dt = u0[0] * t[0] + u0[1] * t[1] + u0[2] * t[2];
                for (int r = 0; r < 3; ++r) u1[r] = t[r] - dt * u0[r];
                n1 = sqrt(u1[0] * u1[0] + u1[1] * u1[1] + u1[2] * u1[2]);
                for (int r = 0; r < 3; ++r) u1[r] /= n1;
            }
            const double u2[3] = {u0[1] * u1[2] - u0[2] * u1[1],
                                  u0[2] * u1[0] - u0[0] * u1[2],
                                  u0[0] * u1[1] - u0[1] * u1[0]};
            // R = u0 v0^T + u1 v1^T + (u0 x u1)(v0 x v1)^T  (sign-invariant Kabsch)
            #pragma unroll
            for (int r = 0; r < 3; ++r)
                #pragma unroll
                for (int c = 0; c < 3; ++c)
                    R[r][c] = u0[r] * v0[c] + u1[r] * v1[c] + u2[r] * v2[c];
        }
    }

    double b2[3];
    #pragma unroll
    for (int d = 0; d < 3; ++d)
        b2[d] = wrc[d] - (wlc[0] * R[0][d] + wlc[1] * R[1][d] + wlc[2] * R[2][d]);

    // Write T: rows 0..2 = [R^T | b2], row 3 = [0 0 0 1]
    float* To = out + OFF_T + (size_t)warp * 16;
    #pragma unroll
    for (int r = 0; r < 3; ++r) {
        To[r * 4 + 0] = (float)R[0][r];
        To[r * 4 + 1] = (float)R[1][r];
        To[r * 4 + 2] = (float)R[2][r];
        To[r * 4 + 3] = (float)b2[r];
    }
    To[12] = 0.0f; To[13] = 0.0f; To[14] = 0.0f; To[15] = 1.0f;

    // ---- D: ||Qh Qh^T - Qg Qg^T||_F = sqrt(8 - 2 ||Lg^{-1} S^T Lh^{-T}||_F^2)
    double Lg[4][4], Lh[4][4];
    for (int r = 0; r < 4; ++r)
        for (int c = 0; c <= r; ++c) {
            double vg = Pg[r][c], vh = Ph[r][c];
            for (int k = 0; k < c; ++k) { vg -= Lg[r][k] * Lg[c][k]; vh -= Lh[r][k] * Lh[c][k]; }
            if (r == c) {
                Lg[r][r] = sqrt(fmax(vg, 1e-32));
                Lh[r][r] = sqrt(fmax(vh, 1e-32));
            } else {
                Lg[r][c] = vg / Lg[c][c];
                Lh[r][c] = vh / Lh[c][c];
            }
        }
    // X = Lg^{-1} S^T   (S^T[r][c] = Sm[c][r] = (G^T H)[r][c])
    double X[4][4];
    for (int c = 0; c < 4; ++c)
        for (int r = 0; r < 4; ++r) {
            double v = Sm[c][r];
            for (int k = 0; k < r; ++k) v -= Lg[r][k] * X[k][c];
            X[r][c] = v / Lg[r][r];
        }
    // Y = Lh^{-1} X^T  => ||Y||_F = ||X Lh^{-T}||_F = ||Qg^T Qh||_F
    double Y[4][4];
    double fro = 0.0;
    for (int c = 0; c < 4; ++c)
        for (int r = 0; r < 4; ++r) {
            double v = X[c][r];
            for (int k = 0; k < r; ++k) v -= Lh[r][k] * Y[k][c];
            Y[r][c] = v / Lh[r][r];
            fro += Y[r][c] * Y[r][c];
        }
    const double Dv = 0.707 * sqrt(fmax(8.0 - 2.0 * fro, 0.0));
    out[OFF_D + warp] = (float)Dv;
}

// ---------------------------------------------------------------------------
extern "C" void kernel_launch(void* const* d_in, const int* in_sizes, int n_in,
                              void* d_out, int out_size)
{
    (void)in_sizes; (void)n_in; (void)out_size;
    const float* sp = (const float*)d_in[0];
    const float* sf = (const float*)d_in[1];
    const float* sk = (const float*)d_in[2];
    const float* tp = (const float*)d_in[3];
    const float* tf = (const float*)d_in[4];
    const float* tk = (const float*)d_in[5];
    float* out = (float*)d_out;

    dim3 g1(BSZ * NKP, 2);
    ume_moments_kernel<<<g1, 256>>>(sp, sf, sk, tp, tf, tk, out);

    const int pairs = BSZ * NKP * NKP;         // 8192
    ume_pair_kernel<<<pairs / 8, 256>>>(out);  // 8 warps (pairs) per block
}

// round 3
// speedup vs baseline: 5.1039x; 5.1039x over previous
#include <cuda_runtime.h>

// ---------------------------------------------------------------------------
// Problem constants (fixed shapes per reference setup_inputs)
// ---------------------------------------------------------------------------
namespace {
constexpr int NPTS = 16384;
constexpr int BSZ  = 2;
constexpr int NKP  = 64;
constexpr int FD   = 64;
constexpr int KNN  = 64;
constexpr float RAD2 = 2.25f;   // 1.5^2

// Output layout: concat of flattened (T, D, G, H)
constexpr int SZ_T  = BSZ * NKP * NKP * 16;   // 131072
constexpr int SZ_D  = BSZ * NKP * NKP;        // 8192
constexpr int SZ_G  = BSZ * NKP * FD * 4;     // 32768
constexpr int OFF_T = 0;
constexpr int OFF_D = SZ_T;
constexpr int OFF_G = OFF_D + SZ_D;
constexpr int OFF_H = OFF_G + SZ_G;

constexpr int SEG = NPTS / 8;                 // 2048 points per warp segment
}

// ---------------------------------------------------------------------------
// Kernel 1: fused ball-query (first-64-by-index within radius) + moment matrix
// One block per (side, b, kp). 256 threads = 8 warps.
// Warp-segmented scan: warp w scans points [w*2048, (w+1)*2048) with NO block
// barriers, collecting up to 64 in-radius indices (in index order) per warp.
// Ordered merge of the 8 per-segment lists == first-64 by global index.
// Moments accumulate in fp64 (precision is load-bearing for the downstream SVD).
// ---------------------------------------------------------------------------
__global__ void __launch_bounds__(256)
ume_moments_kernel(const float* __restrict__ s_pts, const float* __restrict__ s_ft,
                   const float* __restrict__ s_kp,
                   const float* __restrict__ t_pts, const float* __restrict__ t_ft,
                   const float* __restrict__ t_kp,
                   float* __restrict__ out)
{
    const int side = blockIdx.y;
    const float* pts = side ? t_pts : s_pts;
    const float* ft  = side ? t_ft  : s_ft;
    const float* kp  = side ? t_kp  : s_kp;
    float* gout = out + (side ? OFF_H : OFF_G);

    const int b    = blockIdx.x >> 6;
    const int kk   = blockIdx.x & 63;
    const int tid  = threadIdx.x;
    const int lane = tid & 31;
    const int wid  = tid >> 5;

    const float kx = kp[(b * NKP + kk) * 3 + 0];
    const float ky = kp[(b * NKP + kk) * 3 + 1];
    const float kz = kp[(b * NKP + kk) * 3 + 2];

    __shared__ int    s_wl[8][KNN];    // per-warp ordered hit lists
    __shared__ int    s_wc[8];         // per-warp hit counts (capped at 64)
    __shared__ int    s_idx[KNN];      // merged first-64 (sentinel -1)
    __shared__ float  s_red[256];      // per-thread fp64 sums demoted? no: see below
    __shared__ double s_den;

    const float* bp = pts + (size_t)b * NPTS * 3;

    // ---- Phase A: warp-local scan (no block barriers) ----------------------
    {
        const int seg0 = wid * SEG;
        int cnt_w = 0;
        const unsigned lt = (1u << lane) - 1u;
        // 8 mega-rounds of 256 points; 8 batched loads per mega-round (MLP 24)
        for (int mr = 0; mr < 8; ++mr) {
            if (cnt_w >= KNN) break;
            float px[8], py[8], pz[8];
            #pragma unroll
            for (int u = 0; u < 8; ++u) {
                const int j = seg0 + mr * 256 + u * 32 + lane;
                px[u] = bp[3 * j + 0];
                py[u] = bp[3 * j + 1];
                pz[u] = bp[3 * j + 2];
            }
            #pragma unroll
            for (int u = 0; u < 8; ++u) {
                const int j = seg0 + mr * 256 + u * 32 + lane;
                const float dx = px[u] - kx, dy = py[u] - ky, dz = pz[u] - kz;
                const bool hit = (dx * dx + dy * dy + dz * dz) < RAD2;
                const unsigned m = __ballot_sync(0xffffffffu, hit);
                const int pos = cnt_w + __popc(m & lt);
                if (hit && pos < KNN) s_wl[wid][pos] = j;
                cnt_w += __popc(m);
            }
        }
        if (lane == 0) s_wc[wid] = min(cnt_w, KNN);
    }
    __syncthreads();

    // ---- Merge: ordered concat of warp lists, truncated to 64 --------------
    if (tid < KNN) {
        int pre = 0, total = 0;
        #pragma unroll
        for (int ww = 0; ww < 8; ++ww) total += s_wc[ww];
        const int cnt = min(total, KNN);
        int v = -1;
        if (tid < cnt) {
            #pragma unroll
            for (int ww = 0; ww < 8; ++ww) {
                const int c = s_wc[ww];
                if (tid >= pre && tid < pre + c) v = s_wl[ww][tid - pre];
                pre += c;
            }
        }
        s_idx[tid] = v;
    }
    __syncthreads();

    // ---- Phase B: moments (fp64). thread (f,c): c==0 -> m0[f], else m1 -----
    const int f = tid >> 2;
    const int c = tid & 3;
    const float* bft = ft + (size_t)b * NPTS * FD;

    double acc = 0.0;
    #pragma unroll 8
    for (int q = 0; q < KNN; ++q) {
        const int idx = s_idx[q];
        const bool valid = idx >= 0;
        const int i0 = valid ? idx : 0;
        const float wv = valid ? bft[(size_t)i0 * FD + f] : 0.0f;
        const float p  = (c == 0) ? 1.0f : bp[i0 * 3 + (c - 1)];
        acc += (double)wv * (double)p;
    }
    s_red[tid] = (float)acc;                 // only m0 (c==0) lanes are consumed
    __syncthreads();
    if (tid == 0) {
        double ds = 0.0;
        #pragma unroll
        for (int q = 0; q < FD; ++q) ds += (double)s_red[q * 4];  // sum of m0
        s_den = ds + 1e-6;
    }
    __syncthreads();
    gout[((size_t)(b * NKP + kk) * FD + f) * 4 + c] = (float)(acc / s_den);
}

// ---------------------------------------------------------------------------
// Kernel 2: ONE THREAD per (b, i_src, j_tgt) pair. fp64 dot reductions over
// F=64 (S = H^T G, Pg = G^T G, Ph = H^T H), then fp64 epilogue:
// 3x3 Kabsch rotation + translation (T) and subspace distance D via Cholesky
// (equivalent to the reference's QR projector diff).
// Block = one (b, i) row; 64 threads = 64 target keypoints j.
// ---------------------------------------------------------------------------
__global__ void __launch_bounds__(64)
ume_pair_kernel(float* __restrict__ out)
{
    const int b = blockIdx.x >> 6;
    const int i = blockIdx.x & 63;    // source kp
    const int j = threadIdx.x;        // target kp
    const int pair = (blockIdx.x << 6) + j;

    const float4* __restrict__ G = reinterpret_cast<const float4*>(out + OFF_G) + (size_t)(b * NKP + i) * FD;
    const float4* __restrict__ H = reinterpret_cast<const float4*>(out + OFF_H) + (size_t)(b * NKP + j) * FD;

    double S[16], PG[10], PH[10];
    #pragma unroll
    for (int t = 0; t < 16; ++t) S[t] = 0.0;
    #pragma unroll
    for (int t = 0; t < 10; ++t) { PG[t] = 0.0; PH[t] = 0.0; }

    #pragma unroll 2
    for (int f = 0; f < FD; ++f) {
        const float4 gr = __ldg(&G[f]);   // same address across block: broadcast
        const float4 hr = __ldg(&H[f]);
        const double g0 = gr.x, g1 = gr.y, g2 = gr.z, g3 = gr.w;
        const double h0 = hr.x, h1 = hr.y, h2 = hr.z, h3 = hr.w;

        S[0]  += h0 * g0; S[1]  += h0 * g1; S[2]  += h0 * g2; S[3]  += h0 * g3;
        S[4]  += h1 * g0; S[5]  += h1 * g1; S[6]  += h1 * g2; S[7]  += h1 * g3;
        S[8]  += h2 * g0; S[9]  += h2 * g1; S[10] += h2 * g2; S[11] += h2 * g3;
        S[12] += h3 * g0; S[13] += h3 * g1; S[14] += h3 * g2; S[15] += h3 * g3;

        PG[0] += g0 * g0; PG[1] += g1 * g0; PG[2] += g1 * g1;
        PG[3] += g2 * g0; PG[4] += g2 * g1; PG[5] += g2 * g2;
        PG[6] += g3 * g0; PG[7] += g3 * g1; PG[8] += g3 * g2; PG[9] += g3 * g3;

        PH[0] += h0 * h0; PH[1] += h1 * h0; PH[2] += h1 * h1;
        PH[3] += h2 * h0; PH[4] += h2 * h1; PH[5] += h2 * h2;
        PH[6] += h3 * h0; PH[7] += h3 * h1; PH[8] += h3 * h2; PH[9] += h3 * h3;
    }

    // ---- fp64 epilogue -----------------------------------------------------
    double Sm[4][4];
    #pragma unroll
    for (int a = 0; a < 4; ++a)
        #pragma unroll
        for (int bb = 0; bb < 4; ++bb) Sm[a][bb] = S[a * 4 + bb];

    double Pg[4][4], Ph[4][4];
    {
        int idx = 0;
        #pragma unroll
        for (int a = 0; a < 4; ++a)
            #pragma unroll
            for (int bb = 0; bb <= a; ++bb) {
                Pg[a][bb] = Pg[bb][a] = PG[idx];
                Ph[a][bb] = Ph[bb][a] = PH[idx];
                ++idx;
            }
    }

    const double denl = Pg[0][0] + 2e-16;   // mg_sq(+eps) + eps
    const double denr = Sm[0][0] + 1e-16;   // mg_mh + eps
    double wlc[3], wrc[3];
    #pragma unroll
    for (int d = 0; d < 3; ++d) {
        wlc[d] = Pg[d + 1][0] / denl;
        wrc[d] = Sm[d + 1][0] / denr;
    }

    // A = M^T, M[i',j'] = sum_f right[f,i'] left[f,j']
    double A[3][3];
    #pragma unroll
    for (int a = 0; a < 3; ++a)
        #pragma unroll
        for (int bb = 0; bb < 3; ++bb)
            A[a][bb] = Sm[1 + bb][1 + a] - wrc[bb] * Sm[0][1 + a]
                     - wlc[a] * Sm[1 + bb][0] + wrc[bb] * wlc[a] * Sm[0][0];

    // Jacobi eigendecomposition of B = A^T A -> V, then Kabsch rotation.
    double B[3][3];
    #pragma unroll
    for (int r = 0; r < 3; ++r)
        #pragma unroll
        for (int cc = 0; cc < 3; ++cc) {
            double s = 0.0;
            #pragma unroll
            for (int k = 0; k < 3; ++k) s += A[k][r] * A[k][cc];
            B[r][cc] = s;
        }
    double V[3][3] = {{1, 0, 0}, {0, 1, 0}, {0, 0, 1}};
    for (int sweep = 0; sweep < 12; ++sweep) {
        const double off = fabs(B[0][1]) + fabs(B[0][2]) + fabs(B[1][2]);
        const double dia = fabs(B[0][0]) + fabs(B[1][1]) + fabs(B[2][2]);
        if (off <= 1e-28 * (dia + 1e-300)) break;
        #pragma unroll
        for (int pq = 0; pq < 3; ++pq) {
            const int p = (pq == 2) ? 1 : 0;
            const int q = (pq == 0) ? 1 : 2;
            const double bpq = B[p][q];
            if (bpq == 0.0) continue;
            const double tau = (B[q][q] - B[p][p]) / (2.0 * bpq);
            const double t = ((tau >= 0.0) ? 1.0 : -1.0) / (fabs(tau) + sqrt(1.0 + tau * tau));
            const double c = 1.0 / sqrt(1.0 + t * t);
            const double s = t * c;
            #pragma unroll
            for (int k = 0; k < 3; ++k) {
                const double bkp = B[k][p], bkq = B[k][q];
                B[k][p] = c * bkp - s * bkq; B[k][q] = s * bkp + c * bkq;
            }
            #pragma unroll
            for (int k = 0; k < 3; ++k) {
                const double bpk = B[p][k], bqk = B[q][k];
                B[p][k] = c * bpk - s * bqk; B[q][k] = s * bpk + c * bqk;
            }
            #pragma unroll
            for (int k = 0; k < 3; ++k) {
                const double vkp = V[k][p], vkq = V[k][q];
                V[k][p] = c * vkp - s * vkq; V[k][q] = s * vkp + c * vkq;
            }
        }
    }
    // sort eigenvalues descending (track permutation)
    int o0 = 0, o1 = 1, o2 = 2;
    {
        double ea = B[0][0], eb = B[1][1], ec = B[2][2];
        if (ea < eb) { int t = o0; o0 = o1; o1 = t; double u = ea; ea = eb; eb = u; }
        if (ea < ec) { int t = o0; o0 = o2; o2 = t; double u = ea; ea = ec; ec = u; }
        if (eb < ec) { int t = o1; o1 = o2; o2 = t; double u = eb; eb = ec; ec = u; }
    }
    const double v0[3] = {V[0][o0], V[1][o0], V[2][o0]};
    const double v1[3] = {V[0][o1], V[1][o1], V[2][o1]};
    const double v2[3] = {v0[1] * v1[2] - v0[2] * v1[1],
                          v0[2] * v1[0] - v0[0] * v1[2],
                          v0[0] * v1[1] - v0[1] * v1[0]};

    double R[3][3] = {{1, 0, 0}, {0, 1, 0}, {0, 0, 1}};
    {
        double u0[3], u1[3];
        #pragma unroll
        for (int r = 0; r < 3; ++r) {
            u0[r] = A[r][0] * v0[0] + A[r][1] * v0[1] + A[r][2] * v0[2];
            u1[r] = A[r][0] * v1[0] + A[r][1] * v1[1] + A[r][2] * v1[2];
        }
        const double n0 = sqrt(u0[0] * u0[0] + u0[1] * u0[1] + u0[2] * u0[2]);
        if (n0 > 1e-150) {
            #pragma unroll
            for (int r = 0; r < 3; ++r) u0[r] /= n0;
            const double d01 = u0[0] * u1[0] + u0[1] * u1[1] + u0[2] * u1[2];
            #pragma unroll
            for (int r = 0; r < 3; ++r) u1[r] -= d01 * u0[r];
            double n1 = sqrt(u1[0] * u1[0] + u1[1] * u1[1] + u1[2] * u1[2]);
            if (n1 > 1e-14 * n0) {
                #pragma unroll
                for (int r = 0; r < 3; ++r) u1[r] /= n1;
            } else {
                double t[3] = {0, 0, 0};
                t[(fabs(u0[0]) < 0.9) ? 0 : 1] = 1.0;
                const double dt = u0[0] * t[0] + u0[1] * t[1] + u0[2] * t[2];
                #pragma unroll
                for (int r = 0; r < 3; ++r) u1[r] = t[r] - dt * u0[r];
                n1 = sqrt(u1[0] * u1[0] + u1[1] * u1[1] + u1[2] * u1[2]);
                #pragma unroll
                for (int r = 0; r < 3; ++r) u1[r] /= n1;
            }
            const double u2[3] = {u0[1] * u1[2] - u0[2] * u1[1],
                                  u0[2] * u1[0] - u0[0] * u1[2],
                                  u0[0] * u1[1] - u0[1] * u1[0]};
            // R = u0 v0^T + u1 v1^T + (u0 x u1)(v0 x v1)^T  (sign-invariant Kabsch)
            #pragma unroll
            for (int r = 0; r < 3; ++r)
                #pragma unroll
                for (int cc = 0; cc < 3; ++cc)
                    R[r][cc] = u0[r] * v0[cc] + u1[r] * v1[cc] + u2[r] * v2[cc];
        }
    }

    double b2[3];
    #pragma unroll
    for (int d = 0; d < 3; ++d)
        b2[d] = wrc[d] - (wlc[0] * R[0][d] + wlc[1] * R[1][d] + wlc[2] * R[2][d]);

    // Write T: rows 0..2 = [R^T | b2], row 3 = [0 0 0 1]
    float* To = out + OFF_T + (size_t)pair * 16;
    #pragma unroll
    for (int r = 0; r < 3; ++r) {
        To[r * 4 + 0] = (float)R[0][r];
        To[r * 4 + 1] = (float)R[1][r];
        To[r * 4 + 2] = (float)R[2][r];
        To[r * 4 + 3] = (float)b2[r];
    }
    To[12] = 0.0f; To[13] = 0.0f; To[14] = 0.0f; To[15] = 1.0f;

    // ---- D: ||Qh Qh^T - Qg Qg^T||_F = sqrt(8 - 2 ||Lg^{-1} S^T Lh^{-T}||_F^2)
    // In-place Cholesky of Pg, Ph (lower triangles).
    for (int r = 0; r < 4; ++r)
        for (int cc = 0; cc <= r; ++cc) {
            double vg = Pg[r][cc], vh = Ph[r][cc];
            for (int k = 0; k < cc; ++k) { vg -= Pg[r][k] * Pg[cc][k]; vh -= Ph[r][k] * Ph[cc][k]; }
            if (r == cc) {
                Pg[r][r] = sqrt(fmax(vg, 1e-32));
                Ph[r][r] = sqrt(fmax(vh, 1e-32));
            } else {
                Pg[r][cc] = vg / Pg[cc][cc];
                Ph[r][cc] = vh / Ph[cc][cc];
            }
        }
    // X = Lg^{-1} S^T   (S^T[r][c] = Sm[c][r])
    double X[4][4];
    for (int cc = 0; cc < 4; ++cc)
        for (int r = 0; r < 4; ++r) {
            double v = Sm[cc][r];
            for (int k = 0; k < r; ++k) v -= Pg[r][k] * X[k][cc];
            X[r][cc] = v / Pg[r][r];
        }
    // Y col c = Lh^{-1} (X^T col c); accumulate ||Y||_F^2
    double fro = 0.0;
    for (int cc = 0; cc < 4; ++cc) {
        double y[4];
        for (int r = 0; r < 4; ++r) {
            double v = X[cc][r];
            for (int k = 0; k < r; ++k) v -= Ph[r][k] * y[k];
            y[r] = v / Ph[r][r];
            fro += y[r] * y[r];
        }
    }
    const double Dv = 0.707 * sqrt(fmax(8.0 - 2.0 * fro, 0.0));
    out[OFF_D + pair] = (float)Dv;
}

// ---------------------------------------------------------------------------
extern "C" void kernel_launch(void* const* d_in, const int* in_sizes, int n_in,
                              void* d_out, int out_size)
{
    (void)in_sizes; (void)n_in; (void)out_size;
    const float* sp = (const float*)d_in[0];
    const float* sf = (const float*)d_in[1];
    const float* sk = (const float*)d_in[2];
    const float* tp = (const float*)d_in[3];
    const float* tf = (const float*)d_in[4];
    const float* tk = (const float*)d_in[5];
    float* out = (float*)d_out;

    dim3 g1(BSZ * NKP, 2);
    ume_moments_kernel<<<g1, 256>>>(sp, sf, sk, tp, tf, tk, out);

    ume_pair_kernel<<<BSZ * NKP, 64>>>(out);   // one block per (b, i), one thread per pair
}